// round 2
// baseline (speedup 1.0000x reference)
#include <cuda_runtime.h>
#include <cuda_bf16.h>
#include <math_constants.h>

#define HID  128
#define NNODE 50000
#define NEDGE 800000
#define MLPD 512

// ---------------- scratch (static device globals; no runtime alloc) ------------
__device__ __align__(16) float g_mods [(size_t)NNODE * 768];
__device__ __align__(16) float g_xmod [(size_t)NNODE * HID];
__device__ __align__(16) float g_qkv  [(size_t)NNODE * 384];
__device__ __align__(16) float g_score[(size_t)NEDGE * 8];
__device__ __align__(16) float g_smax [(size_t)NNODE * 8];
__device__ __align__(16) float g_den  [(size_t)NNODE * 8];
__device__ __align__(16) float g_attn [(size_t)NNODE * HID];
__device__ __align__(16) float g_x1   [(size_t)NNODE * HID];
__device__ __align__(16) float g_h    [(size_t)NNODE * MLPD];
__device__ int g_src[NEDGE];
__device__ int g_dst[NEDGE];
__device__ int g_is32;

// ---------------- helpers ------------------------------------------------------
__device__ __forceinline__ float siluf(float v) {
    return v / (1.0f + __expf(-v));
}
__device__ __forceinline__ float gelu_tanh(float v) {
    float v3 = v * v * v;
    float t = tanhf(0.7978845608028654f * (v + 0.044715f * v3));
    return 0.5f * v * (1.0f + t);
}
__device__ __forceinline__ void atomicMaxFloat(float* addr, float val) {
    if (val >= 0.0f) {
        atomicMax((int*)addr, __float_as_int(val));
    } else {
        atomicMin((unsigned int*)addr, (unsigned int)__float_as_int(val));
    }
}

// ---------------- edge-index dtype detection + conversion ----------------------
// If the buffer holds int64 node ids, every 8-byte value is in [0, NNODE).
// If it holds int32 ids, an 8-byte read packs two random ids -> >= 2^32 almost
// surely. Scan 256 values (always within the buffer for either dtype).
__global__ void detect_kernel(const void* ei_raw) {
    const long long* p = (const long long*)ei_raw;
    int bad = 0;
    for (int i = threadIdx.x; i < 256; i += blockDim.x) {
        long long v = p[i];
        if (v < 0 || v >= NNODE) bad = 1;
    }
    bad = __syncthreads_or(bad);
    if (threadIdx.x == 0) g_is32 = bad;
}

__global__ void convert_kernel(const void* ei_raw) {
    int e = blockIdx.x * blockDim.x + threadIdx.x;
    if (e >= NEDGE) return;
    if (g_is32) {
        const int* p = (const int*)ei_raw;
        g_src[e] = p[e];
        g_dst[e] = p[NEDGE + e];
    } else {
        const long long* p = (const long long*)ei_raw;
        g_src[e] = (int)p[e];
        g_dst[e] = (int)p[NEDGE + e];
    }
}

// ---------------- init ---------------------------------------------------------
__global__ void init_kernel() {
    int i = blockIdx.x * blockDim.x + threadIdx.x;
    if (i < NNODE * HID) g_attn[i] = 0.0f;
    if (i < NNODE * 8) {
        g_smax[i] = -CUDART_INF_F;
        g_den[i]  = 0.0f;
    }
}

// ---------------- LayerNorm + modulate -----------------------------------------
__global__ void ln_mod_kernel(const float* __restrict__ X,
                              int shift_off, int scale_off,
                              float* __restrict__ out) {
    int warp = (blockIdx.x * blockDim.x + threadIdx.x) >> 5;
    if (warp >= NNODE) return;
    int lane = threadIdx.x & 31;
    const float4 v = *(const float4*)(X + (size_t)warp * HID + lane * 4);
    float s  = v.x + v.y + v.z + v.w;
    float sq = v.x * v.x + v.y * v.y + v.z * v.z + v.w * v.w;
    #pragma unroll
    for (int o = 16; o > 0; o >>= 1) {
        s  += __shfl_xor_sync(0xffffffffu, s,  o);
        sq += __shfl_xor_sync(0xffffffffu, sq, o);
    }
    float mean = s * (1.0f / HID);
    float var  = sq * (1.0f / HID) - mean * mean;
    float rstd = rsqrtf(var + 1e-6f);
    const float4 sh = *(const float4*)(g_mods + (size_t)warp * 768 + shift_off + lane * 4);
    const float4 sc = *(const float4*)(g_mods + (size_t)warp * 768 + scale_off + lane * 4);
    float4 o4;
    o4.x = (v.x - mean) * rstd * (1.0f + sc.x) + sh.x;
    o4.y = (v.y - mean) * rstd * (1.0f + sc.y) + sh.y;
    o4.z = (v.z - mean) * rstd * (1.0f + sc.z) + sh.z;
    o4.w = (v.w - mean) * rstd * (1.0f + sc.w) + sh.w;
    *(float4*)(out + (size_t)warp * HID + lane * 4) = o4;
}

// ---------------- SGEMM 128x128x16, 256 thr, 8x8 per thread --------------------
// AACT: 0=none 1=silu on A.   EPI: 0=none 1=gelu 2=res+gate*(acc+bias)
template<int AACT, int EPI>
__global__ __launch_bounds__(256)
void sgemm_kernel(const float* __restrict__ A, const float* __restrict__ B,
                  const float* __restrict__ bias,
                  const float* __restrict__ gate,   // row stride 768 (EPI==2)
                  const float* __restrict__ res,    // row stride N   (EPI==2)
                  float* __restrict__ C,
                  int M, int N, int K) {
    __shared__ float As[16][128];
    __shared__ float Bs[16][128];
    const int tid = threadIdx.x;
    const int row0 = blockIdx.y * 128;
    const int col0 = blockIdx.x * 128;
    const int tx = tid & 15, ty = tid >> 4;

    float acc[8][8];
    #pragma unroll
    for (int i = 0; i < 8; i++)
        #pragma unroll
        for (int j = 0; j < 8; j++) acc[i][j] = 0.0f;

    const int arow = tid >> 2;          // 0..63
    const int acol = (tid & 3) << 2;    // 0,4,8,12
    const int brow = tid >> 5;          // 0..7
    const int bcol = (tid & 31) << 2;   // 0..124

    for (int k0 = 0; k0 < K; k0 += 16) {
        #pragma unroll
        for (int r = 0; r < 2; r++) {
            int gr = row0 + arow + r * 64;
            float4 a = make_float4(0.f, 0.f, 0.f, 0.f);
            if (gr < M) a = *(const float4*)(A + (size_t)gr * K + k0 + acol);
            if (AACT == 1) {
                a.x = siluf(a.x); a.y = siluf(a.y);
                a.z = siluf(a.z); a.w = siluf(a.w);
            }
            As[acol + 0][arow + r * 64] = a.x;
            As[acol + 1][arow + r * 64] = a.y;
            As[acol + 2][arow + r * 64] = a.z;
            As[acol + 3][arow + r * 64] = a.w;
        }
        #pragma unroll
        for (int r = 0; r < 2; r++) {
            int gk = k0 + brow + r * 8;
            float4 b = *(const float4*)(B + (size_t)gk * N + col0 + bcol);
            *(float4*)&Bs[brow + r * 8][bcol] = b;
        }
        __syncthreads();
        #pragma unroll
        for (int kk = 0; kk < 16; kk++) {
            float ra[8], rb[8];
            *(float4*)(ra)     = *(const float4*)&As[kk][ty * 8];
            *(float4*)(ra + 4) = *(const float4*)&As[kk][ty * 8 + 4];
            *(float4*)(rb)     = *(const float4*)&Bs[kk][tx * 8];
            *(float4*)(rb + 4) = *(const float4*)&Bs[kk][tx * 8 + 4];
            #pragma unroll
            for (int i = 0; i < 8; i++)
                #pragma unroll
                for (int j = 0; j < 8; j++)
                    acc[i][j] += ra[i] * rb[j];
        }
        __syncthreads();
    }

    #pragma unroll
    for (int i = 0; i < 8; i++) {
        int gr = row0 + ty * 8 + i;
        if (gr >= M) break;
        #pragma unroll
        for (int j = 0; j < 8; j += 4) {
            int gc = col0 + tx * 8 + j;
            float4 v;
            v.x = acc[i][j + 0]; v.y = acc[i][j + 1];
            v.z = acc[i][j + 2]; v.w = acc[i][j + 3];
            if (bias != nullptr) {
                v.x += bias[gc + 0]; v.y += bias[gc + 1];
                v.z += bias[gc + 2]; v.w += bias[gc + 3];
            }
            if (EPI == 1) {
                v.x = gelu_tanh(v.x); v.y = gelu_tanh(v.y);
                v.z = gelu_tanh(v.z); v.w = gelu_tanh(v.w);
            } else if (EPI == 2) {
                const float4 g4 = *(const float4*)(gate + (size_t)gr * 768 + gc);
                const float4 r4 = *(const float4*)(res + (size_t)gr * N + gc);
                v.x = r4.x + g4.x * v.x;
                v.y = r4.y + g4.y * v.y;
                v.z = r4.z + g4.z * v.z;
                v.w = r4.w + g4.w * v.w;
            }
            *(float4*)(C + (size_t)gr * N + gc) = v;
        }
    }
}

// ---------------- edge pass 1: scores + segment max ----------------------------
__global__ void edge_score_kernel() {
    int e = (blockIdx.x * blockDim.x + threadIdx.x) >> 5;
    if (e >= NEDGE) return;
    int lane = threadIdx.x & 31;
    int src = g_src[e];
    int dst = g_dst[e];
    const float4 q = *(const float4*)(g_qkv + (size_t)dst * 384 + lane * 4);
    const float4 k = *(const float4*)(g_qkv + (size_t)src * 384 + 128 + lane * 4);
    float p = q.x * k.x + q.y * k.y + q.z * k.z + q.w * k.w;
    p += __shfl_xor_sync(0xffffffffu, p, 1);
    p += __shfl_xor_sync(0xffffffffu, p, 2);
    if ((lane & 3) == 0) {
        int h = lane >> 2;
        float s = p * 0.25f;  // / sqrt(16)
        g_score[(size_t)e * 8 + h] = s;
        atomicMaxFloat(&g_smax[(size_t)dst * 8 + h], s);
    }
}

// ---------------- edge pass 2: exp + segment sum -------------------------------
__global__ void edge_softmax_kernel() {
    int i = blockIdx.x * blockDim.x + threadIdx.x;
    if (i >= NEDGE * 8) return;
    int e = i >> 3, h = i & 7;
    int dst = g_dst[e];
    float ex = __expf(g_score[i] - g_smax[(size_t)dst * 8 + h]);
    g_score[i] = ex;
    atomicAdd(&g_den[(size_t)dst * 8 + h], ex);
}

// ---------------- edge pass 3: weighted aggregate ------------------------------
__global__ void edge_agg_kernel() {
    int e = (blockIdx.x * blockDim.x + threadIdx.x) >> 5;
    if (e >= NEDGE) return;
    int lane = threadIdx.x & 31;
    int src = g_src[e];
    int dst = g_dst[e];
    int h = lane >> 2;
    float a = g_score[(size_t)e * 8 + h];
    float d = g_den[(size_t)dst * 8 + h];
    float w = a / d;
    const float4 v = *(const float4*)(g_qkv + (size_t)src * 384 + 256 + lane * 4);
    float* p = g_attn + (size_t)dst * HID + lane * 4;
    asm volatile("red.global.add.v4.f32 [%0], {%1, %2, %3, %4};"
                 :: "l"(p), "f"(v.x * w), "f"(v.y * w), "f"(v.z * w), "f"(v.w * w)
                 : "memory");
}

// ---------------- launch -------------------------------------------------------
static inline int cdiv(int a, int b) { return (a + b - 1) / b; }

extern "C" void kernel_launch(void* const* d_in, const int* in_sizes, int n_in,
                              void* d_out, int out_size) {
    const float* x      = (const float*)d_in[0];
    const void*  ei     = d_in[1];                 // int32 or int64 (detected)
    const float* c      = (const float*)d_in[2];
    const float* w_qkv  = (const float*)d_in[3];
    const float* w_proj = (const float*)d_in[4];
    const float* b_proj = (const float*)d_in[5];
    const float* w_mlp1 = (const float*)d_in[6];
    const float* b_mlp1 = (const float*)d_in[7];
    const float* w_mlp2 = (const float*)d_in[8];
    const float* b_mlp2 = (const float*)d_in[9];
    const float* w_ada  = (const float*)d_in[10];
    const float* b_ada  = (const float*)d_in[11];
    float*       out    = (float*)d_out;

    float *mods, *xmod, *qkv, *x1, *h, *attn;
    cudaGetSymbolAddress((void**)&mods, g_mods);
    cudaGetSymbolAddress((void**)&xmod, g_xmod);
    cudaGetSymbolAddress((void**)&qkv,  g_qkv);
    cudaGetSymbolAddress((void**)&x1,   g_x1);
    cudaGetSymbolAddress((void**)&h,    g_h);
    cudaGetSymbolAddress((void**)&attn, g_attn);

    // edge index normalization + accumulator init
    detect_kernel<<<1, 256>>>(ei);
    convert_kernel<<<cdiv(NEDGE, 256), 256>>>(ei);
    init_kernel<<<cdiv(NNODE * HID, 256), 256>>>();

    // mods = silu(c) @ w_ada + b_ada            [N, 768]
    sgemm_kernel<1, 0><<<dim3(768 / 128, cdiv(NNODE, 128)), 256>>>(
        c, w_ada, b_ada, nullptr, nullptr, mods, NNODE, 768, HID);

    // xmod = modulate(LN(x), sh_msa, sc_msa)
    ln_mod_kernel<<<cdiv(NNODE * 32, 256), 256>>>(x, 0, 128, xmod);

    // qkv = xmod @ w_qkv                         [N, 384]
    sgemm_kernel<0, 0><<<dim3(384 / 128, cdiv(NNODE, 128)), 256>>>(
        xmod, w_qkv, nullptr, nullptr, nullptr, qkv, NNODE, 384, HID);

    // graph attention
    edge_score_kernel  <<<cdiv(NEDGE * 32, 256), 256>>>();
    edge_softmax_kernel<<<cdiv(NEDGE * 8, 256), 256>>>();
    edge_agg_kernel    <<<cdiv(NEDGE * 32, 256), 256>>>();

    // x1 = x + g_msa * (attn @ w_proj + b_proj)
    sgemm_kernel<0, 2><<<dim3(1, cdiv(NNODE, 128)), 256>>>(
        attn, w_proj, b_proj, mods + 256, x, x1, NNODE, HID, HID);

    // hmod = modulate(LN(x1), sh_mlp, sc_mlp)   (reuse xmod buffer)
    ln_mod_kernel<<<cdiv(NNODE * 32, 256), 256>>>(x1, 384, 512, xmod);

    // h = gelu(hmod @ w_mlp1 + b_mlp1)          [N, 512]
    sgemm_kernel<0, 1><<<dim3(MLPD / 128, cdiv(NNODE, 128)), 256>>>(
        xmod, w_mlp1, b_mlp1, nullptr, nullptr, h, NNODE, MLPD, HID);

    // out = x1 + g_mlp * (h @ w_mlp2 + b_mlp2)
    sgemm_kernel<0, 2><<<dim3(1, cdiv(NNODE, 128)), 256>>>(
        h, w_mlp2, b_mlp2, mods + 640, x1, out, NNODE, HID, MLPD);
}